// round 5
// baseline (speedup 1.0000x reference)
#include <cuda_runtime.h>
#include <cuda_bf16.h>
#include <cstdint>

// ---------------- problem constants ----------------
#define NV   16384
#define KC   8192
#define DIMV 256
#define HWSZ 1024
#define BDHW (DIMV*HWSZ)

#define DECAYF 0.99f
#define OMDF   0.01f
#define EPSF   1e-5f
#define TCAND  1.5f     // candidate threshold (>= 14 sigma of bf16 1-pass error)
#define CAP    24       // candidate capacity per row

// output layout (float32, concatenated)
#define OUT_OFF  0
#define LOSS_OFF 4194304
#define IDX_OFF  4194305
#define CS_OFF   4210689
#define EMAW_OFF 4218881
#define EMB_OFF  6316033

// ---------------- scratch ----------------
__device__ __nv_bfloat16 g_zh[NV * DIMV];   // token-major bf16 z
__device__ __nv_bfloat16 g_eh[KC * DIMV];   // bf16 codebook
__device__ float  g_enorm[KC];
__device__ int    g_idx[NV];
__device__ float  g_esum[KC * DIMV];
__device__ float  g_counts[KC];
__device__ double g_loss;
__device__ float  g_ncs[KC];
__device__ int    g_nflag;
__device__ int    g_flaglist[NV];

// ---------------- helpers ----------------
__device__ __forceinline__ uint32_t smem_u32(const void* p) {
    uint32_t a;
    asm("{ .reg .u64 t; cvta.to.shared.u64 t, %1; cvt.u32.u64 %0, t; }" : "=r"(a) : "l"(p));
    return a;
}
#define CP_ASYNC16(sm, gp) asm volatile("cp.async.cg.shared.global [%0], [%1], 16;" :: "r"(sm), "l"(gp) : "memory")
#define CP_COMMIT() asm volatile("cp.async.commit_group;" ::: "memory")
#define CP_WAIT1()  asm volatile("cp.async.wait_group 1;" ::: "memory")

__device__ __forceinline__ void ldsm4(uint32_t& r0, uint32_t& r1, uint32_t& r2, uint32_t& r3, uint32_t a) {
    asm volatile("ldmatrix.sync.aligned.m8n8.x4.shared.b16 {%0,%1,%2,%3}, [%4];"
                 : "=r"(r0), "=r"(r1), "=r"(r2), "=r"(r3) : "r"(a));
}
__device__ __forceinline__ void mma16816(float& c0, float& c1, float& c2, float& c3,
                                         uint32_t a0, uint32_t a1, uint32_t a2, uint32_t a3,
                                         uint32_t b0, uint32_t b1) {
    asm volatile("mma.sync.aligned.m16n8k16.row.col.f32.bf16.bf16.f32 "
                 "{%0,%1,%2,%3}, {%4,%5,%6,%7}, {%8,%9}, {%0,%1,%2,%3};"
                 : "+f"(c0), "+f"(c1), "+f"(c2), "+f"(c3)
                 : "r"(a0), "r"(a1), "r"(a2), "r"(a3), "r"(b0), "r"(b1));
}
__device__ __forceinline__ uint32_t fkey(float s) {
    uint32_t b = __float_as_uint(s);
    return (b & 0x80000000u) ? ~b : (b | 0x80000000u);
}
__device__ __forceinline__ float funkey(uint32_t k) {
    return (k & 0x80000000u) ? __uint_as_float(k ^ 0x80000000u) : __uint_as_float(~k);
}

// smem layout (relative to 1024-aligned base). 64 tokens/CTA, NT=64 codes/tile
#define MTOK   64
#define NT     64
#define TILES  (KC / NT)          // 128
#define SA     0                  // A: 64 x 512B = 32768
#define SB     32768              // B: 2 x 32768
#define SMK64  (SB + 65536)       // 64 x u64 = 512
#define SROWK  (SMK64 + 512)      // 64 x u32 = 256
#define SCNT   (SROWK + 256)      // 64 x int = 256
#define SCODE  (SCNT + 256)       // 64 x CAP x 4 = 6144
#define SSV    (SCODE + 64*CAP*4) // 6144
#define SM_SZ  (SSV + 64*CAP*4 + 1024)

// ---------------------------------------------------------------------------
// P1: z [16,256,32,32] -> token-major bf16 (32x32 transpose tiles)
// ---------------------------------------------------------------------------
__global__ void p_zsplit(const float* __restrict__ z) {
    __shared__ float tile[32][33];
    int b = blockIdx.z, d0 = blockIdx.y * 32, hw0 = blockIdx.x * 32;
    int tx = threadIdx.x, ty = threadIdx.y;
    #pragma unroll
    for (int k = 0; k < 4; k++) {
        int d = d0 + ty + k * 8;
        tile[ty + k * 8][tx] = z[b * BDHW + d * HWSZ + hw0 + tx];
    }
    __syncthreads();
    #pragma unroll
    for (int k = 0; k < 4; k++) {
        int hw = hw0 + ty + k * 8;
        int n = b * HWSZ + hw;
        g_zh[n * DIMV + d0 + tx] = __float2bfloat16(tile[tx][ty + k * 8]);
    }
}

// ---------------------------------------------------------------------------
// P2: e -> bf16 + ||e||^2
// ---------------------------------------------------------------------------
__global__ void p_esplit(const float* __restrict__ e) {
    int w = (blockIdx.x * blockDim.x + threadIdx.x) >> 5;
    int lane = threadIdx.x & 31;
    if (w >= KC) return;
    const float* row = e + w * DIMV;
    float s = 0.f;
    #pragma unroll
    for (int i = 0; i < 8; i++) {
        int d = i * 32 + lane;
        float x = row[d];
        g_eh[w * DIMV + d] = __float2bfloat16(x);
        s += x * x;
    }
    #pragma unroll
    for (int o = 16; o; o >>= 1) s += __shfl_xor_sync(0xFFFFFFFFu, s, o);
    if (lane == 0) g_enorm[w] = s;
}

// ---------------------------------------------------------------------------
// K0: zero accumulators
// ---------------------------------------------------------------------------
__global__ void k_zero() {
    int i = blockIdx.x * blockDim.x + threadIdx.x;
    int stride = gridDim.x * blockDim.x;
    for (int j = i; j < KC * DIMV; j += stride) g_esum[j] = 0.f;
    for (int j = i; j < KC; j += stride) g_counts[j] = 0.f;
    if (i == 0) { g_loss = 0.0; g_nflag = 0; }
}

// ---------------------------------------------------------------------------
// K1: bf16 mma.sync GEMM (64 tokens x 8192 codes x 256) + candidate argmin.
// 128 threads = 4 warps, warp grid 2(M) x 2(N), warp tile 32x32, NT=64.
// Register-only per-tile epilogue: per-thread running min over own code
// subset; append codes with v < min(own_min, stale_row_min) + T. Superset
// guarantee: own_min >= global min, so every code within T of the global
// approx min is appended. Exact fp32 re-score of survivors at the end.
// ---------------------------------------------------------------------------
__global__ void __launch_bounds__(128, 2)
k_dist_mma(const float* __restrict__ z, const float* __restrict__ e,
           float* __restrict__ out) {
    extern __shared__ char dsm[];
    uint32_t raw = smem_u32(dsm);
    uint32_t base = (raw + 1023u) & ~1023u;
    char* sm = dsm + (base - raw);

    int tid = threadIdx.x;
    int lane = tid & 31, wid = tid >> 5;
    int wm = wid & 1, wn = wid >> 1;
    int n0 = blockIdx.x * MTOK;

    unsigned long long* mkey64 = (unsigned long long*)(sm + SMK64);
    uint32_t* rowk = (uint32_t*)(sm + SROWK);
    int* cnt_sm = (int*)(sm + SCNT);
    int* scode = (int*)(sm + SCODE);
    float* ssv = (float*)(sm + SSV);

    if (tid < 64) {
        cnt_sm[tid] = 0;
        rowk[tid] = 0xFFFFFFFFu;
        mkey64[tid] = 0xFFFFFFFFFFFFFFFFull;
    }

    // ---- prologue: A (64 token rows) + B tiles 0,1 via cp.async ----
    #pragma unroll
    for (int i = 0; i < 16; i++) {
        int idx = tid + 128 * i;
        int row = idx >> 5, kc = idx & 31;
        uint32_t sa = base + SA + row * 512 + (((uint32_t)(kc << 4)) ^ ((row & 7) << 4));
        CP_ASYNC16(sa, (const void*)(g_zh + (size_t)(n0 + row) * DIMV + kc * 8));
    }
    #pragma unroll
    for (int i = 0; i < 16; i++) {
        int idx = tid + 128 * i;
        int row = idx >> 5, kc = idx & 31;
        uint32_t sa = base + SB + row * 512 + (((uint32_t)(kc << 4)) ^ ((row & 7) << 4));
        CP_ASYNC16(sa, (const void*)(g_eh + (size_t)row * DIMV + kc * 8));
    }
    CP_COMMIT();
    #pragma unroll
    for (int i = 0; i < 16; i++) {
        int idx = tid + 128 * i;
        int row = idx >> 5, kc = idx & 31;
        uint32_t sa = base + SB + 32768 + row * 512 + (((uint32_t)(kc << 4)) ^ ((row & 7) << 4));
        CP_ASYNC16(sa, (const void*)(g_eh + (size_t)(NT + row) * DIMV + kc * 8));
    }
    CP_COMMIT();

    // ldmatrix per-thread address pieces
    int grp = lane >> 3;
    int rA_off = (lane & 7) + ((grp & 1) << 3);
    uint32_t boA = (uint32_t)((grp >> 1) << 4);
    int rB_off = (lane & 7) + ((grp >> 1) << 3);
    uint32_t boB = (uint32_t)((grp & 1) << 4);

    uint32_t aRow[2], aSw[2];
    #pragma unroll
    for (int mf = 0; mf < 2; mf++) {
        int r = wm * 32 + mf * 16 + rA_off;
        aRow[mf] = base + SA + r * 512;
        aSw[mf] = (uint32_t)((r & 7) << 4);
    }
    uint32_t bRow[2], bSw[2];
    #pragma unroll
    for (int p = 0; p < 2; p++) {
        int r = wn * 32 + p * 16 + rB_off;
        bRow[p] = r * 512;
        bSw[p] = (uint32_t)((r & 7) << 4);
    }

    // rows owned by this thread: q = mf*2 + h
    int rown[4];
    #pragma unroll
    for (int mf = 0; mf < 2; mf++)
        #pragma unroll
        for (int h = 0; h < 2; h++)
            rown[mf * 2 + h] = wm * 32 + mf * 16 + (lane >> 2) + h * 8;

    float rm[4] = {3.4e38f, 3.4e38f, 3.4e38f, 3.4e38f};
    unsigned long long bk[4] = {~0ull, ~0ull, ~0ull, ~0ull};
    float acc[32];
    int cbase_th = wn * 32 + 2 * (lane & 3);   // + nf*8 + co

    for (int t = 0; t < TILES; t++) {
        CP_WAIT1();
        __syncthreads();

        // prefetch enorms for this tile (used after the mma loop)
        float en[8];
        #pragma unroll
        for (int nf = 0; nf < 4; nf++)
            #pragma unroll
            for (int co = 0; co < 2; co++)
                en[nf * 2 + co] = __ldg(&g_enorm[t * NT + cbase_th + nf * 8 + co]);

        #pragma unroll
        for (int i = 0; i < 32; i++) acc[i] = 0.f;

        uint32_t bbuf = base + SB + (uint32_t)(t & 1) * 32768u;

        #pragma unroll
        for (int ks = 0; ks < 16; ks++) {
            uint32_t kb = (uint32_t)(ks * 32);
            uint32_t a0[2], a1[2], a2[2], a3[2];
            #pragma unroll
            for (int mf = 0; mf < 2; mf++)
                ldsm4(a0[mf], a1[mf], a2[mf], a3[mf], aRow[mf] + ((kb + boA) ^ aSw[mf]));
            uint32_t b0[4], b1[4];
            #pragma unroll
            for (int p = 0; p < 2; p++) {
                uint32_t r0, r1, r2, r3;
                ldsm4(r0, r1, r2, r3, bbuf + bRow[p] + ((kb + boB) ^ bSw[p]));
                b0[p * 2] = r0; b1[p * 2] = r1; b0[p * 2 + 1] = r2; b1[p * 2 + 1] = r3;
            }
            #pragma unroll
            for (int mf = 0; mf < 2; mf++)
                #pragma unroll
                for (int nf = 0; nf < 4; nf++) {
                    int ix = mf * 16 + nf * 4;
                    mma16816(acc[ix], acc[ix + 1], acc[ix + 2], acc[ix + 3],
                             a0[mf], a1[mf], a2[mf], a3[mf], b0[nf], b1[nf]);
                }
        }

        __syncthreads();   // all ldsm reads of buf (t&1) done

        // prefetch tile t+2 into buf (t&1); overlaps epilogue
        if (t + 2 < TILES) {
            uint32_t db = base + SB + (uint32_t)(t & 1) * 32768u;
            const __nv_bfloat16* gsrc = g_eh + (size_t)(t + 2) * NT * DIMV;
            #pragma unroll
            for (int i = 0; i < 16; i++) {
                int idx = tid + 128 * i;
                int row = idx >> 5, kc = idx & 31;
                uint32_t sa = db + row * 512 + (((uint32_t)(kc << 4)) ^ ((row & 7) << 4));
                CP_ASYNC16(sa, (const void*)(gsrc + (size_t)row * DIMV + kc * 8));
            }
        }
        CP_COMMIT();

        // ---- register-only epilogue ----
        #pragma unroll
        for (int mf = 0; mf < 2; mf++)
            #pragma unroll
            for (int h = 0; h < 2; h++) {
                int q = mf * 2 + h;
                int r = rown[q];
                float thf = fminf(rm[q], funkey(rowk[r])) + TCAND;
                #pragma unroll
                for (int nf = 0; nf < 4; nf++)
                    #pragma unroll
                    for (int co = 0; co < 2; co++) {
                        float v = fmaf(-2.f, acc[mf * 16 + nf * 4 + h * 2 + co], en[nf * 2 + co]);
                        if (v < thf) {
                            int code = t * NT + cbase_th + nf * 8 + co;
                            int p = atomicAdd(&cnt_sm[r], 1);
                            if (p < CAP) { scode[r * CAP + p] = code; ssv[r * CAP + p] = v; }
                            if (v < rm[q]) {
                                rm[q] = v;
                                thf = fminf(thf, v + TCAND);
                                bk[q] = ((unsigned long long)fkey(v) << 32) | (unsigned int)code;
                            }
                        }
                    }
                if ((t & 7) == 7) atomicMin(&rowk[r], fkey(rm[q]));
            }
    }

    // publish per-thread bests, then exact re-score
    #pragma unroll
    for (int q = 0; q < 4; q++) atomicMin(&mkey64[rown[q]], bk[q]);
    __syncthreads();

    if (tid < 64) {
        int token = n0 + tid;
        int c = cnt_sm[tid];
        if (c > CAP) {
            int fi = atomicAdd(&g_nflag, 1);
            g_flaglist[fi] = token;
            c = CAP;
        }
        float th = funkey((uint32_t)(mkey64[tid] >> 32)) + TCAND;
        int b = token >> 10, hw = token & 1023;
        const float* zb = z + (size_t)b * BDHW + hw;
        float bestS = 3.4e38f; int bestC = 0x7fffffff;
        for (int i = 0; i < c; i++) {
            if (ssv[tid * CAP + i] <= th) {
                int code = scode[tid * CAP + i];
                const float* er = e + (size_t)code * DIMV;
                float dot = 0.f;
                #pragma unroll 8
                for (int d = 0; d < DIMV; d++) dot = fmaf(zb[d * HWSZ], er[d], dot);
                float s = __ldg(&g_enorm[code]) - 2.f * dot;
                if (s < bestS || (s == bestS && code < bestC)) { bestS = s; bestC = code; }
            }
        }
        g_idx[token] = bestC;
        out[IDX_OFF + token] = (float)bestC;
    }
}

// ---------------------------------------------------------------------------
// K1b: rescue — exact full scan for overflowed tokens (expected none)
// ---------------------------------------------------------------------------
__global__ void __launch_bounds__(256)
k_rescue(const float* __restrict__ z, const float* __restrict__ e,
         float* __restrict__ out) {
    __shared__ float zr[256];
    __shared__ unsigned long long red[256];
    int nf = g_nflag;
    for (int f = blockIdx.x; f < nf; f += gridDim.x) {
        int token = g_flaglist[f];
        int b = token >> 10, hw = token & 1023;
        zr[threadIdx.x] = z[(size_t)b * BDHW + threadIdx.x * HWSZ + hw];
        __syncthreads();
        unsigned long long best = 0xFFFFFFFFFFFFFFFFull;
        for (int c = threadIdx.x; c < KC; c += 256) {
            const float* er = e + (size_t)c * DIMV;
            float dot = 0.f;
            #pragma unroll 8
            for (int d = 0; d < DIMV; d++) dot = fmaf(zr[d], er[d], dot);
            float s = g_enorm[c] - 2.f * dot;
            unsigned long long p = ((unsigned long long)fkey(s) << 32) | (unsigned int)c;
            best = min(best, p);
        }
        red[threadIdx.x] = best;
        __syncthreads();
        for (int s = 128; s; s >>= 1) {
            if (threadIdx.x < s) red[threadIdx.x] = min(red[threadIdx.x], red[threadIdx.x + s]);
            __syncthreads();
        }
        if (threadIdx.x == 0) {
            int bc = (int)(red[0] & 0xFFFFFFFFu);
            g_idx[token] = bc;
            out[IDX_OFF + token] = (float)bc;
        }
        __syncthreads();
    }
}

// ---------------------------------------------------------------------------
// K2: gather/scatter. grid (token_block, d_chunk of 32)
// ---------------------------------------------------------------------------
__global__ void __launch_bounds__(128)
k_scatter(const float* __restrict__ z, const float* __restrict__ e,
          float* __restrict__ out) {
    int t = threadIdx.x;
    int n = blockIdx.x * 128 + t;
    int d0 = blockIdx.y * 32;
    int idx = g_idx[n];
    if (blockIdx.y == 0) atomicAdd(&g_counts[idx], 1.f);

    int b = n >> 10, hw = n & 1023;
    const float* zb = z + (size_t)b * BDHW + hw;
    float*       ob = out + OUT_OFF + (size_t)b * BDHW + hw;
    const float* er = e + (size_t)idx * DIMV;
    float* es = g_esum + (size_t)idx * DIMV;

    float lacc = 0.f;
    #pragma unroll
    for (int i = 0; i < 32; i++) {
        int d = d0 + i;
        float zv = zb[d * HWSZ];
        float diff = er[d] - zv;
        lacc += diff * diff;
        ob[d * HWSZ] = zv + diff;
        atomicAdd(&es[d], zv);
    }

    __shared__ float red[128];
    red[t] = lacc;
    __syncthreads();
    #pragma unroll
    for (int s = 64; s; s >>= 1) {
        if (t < s) red[t] += red[t + s];
        __syncthreads();
    }
    if (t == 0) atomicAdd(&g_loss, (double)red[0]);
}

// ---------------------------------------------------------------------------
// K3: cluster-size EMA + denom + loss finalize
// ---------------------------------------------------------------------------
__global__ void __launch_bounds__(1024)
k_cs(const float* __restrict__ cluster_size, float* __restrict__ out) {
    __shared__ float red[1024];
    int t = threadIdx.x;
    float csl[8];
    float local = 0.f;
    #pragma unroll
    for (int r = 0; r < 8; r++) {
        int k = t * 8 + r;
        float cs = cluster_size[k] * DECAYF + OMDF * g_counts[k] + EPSF;
        csl[r] = cs;
        local += cs;
    }
    red[t] = local;
    __syncthreads();
    #pragma unroll
    for (int s = 512; s; s >>= 1) {
        if (t < s) red[t] += red[t + s];
        __syncthreads();
    }
    float denom = red[0] + (float)(KC * 1e-05);
    #pragma unroll
    for (int r = 0; r < 8; r++) {
        int k = t * 8 + r;
        float v = csl[r] / denom;
        g_ncs[k] = v;
        out[CS_OFF + k] = v;
    }
    if (t == 0)
        out[LOSS_OFF] = (float)(0.25 * g_loss / (double)((size_t)NV * DIMV));
}

// ---------------------------------------------------------------------------
// K4: new_ema_w and new_embedding
// ---------------------------------------------------------------------------
__global__ void k_final(const float* __restrict__ ema_w, float* __restrict__ out) {
    int i = blockIdx.x * blockDim.x + threadIdx.x;
    if (i >= KC * DIMV) return;
    int k = i >> 8;
    float v = ema_w[i] * DECAYF + OMDF * g_esum[i];
    out[EMAW_OFF + i] = v;
    out[EMB_OFF + i]  = v / g_ncs[k];
}

// ---------------------------------------------------------------------------
extern "C" void kernel_launch(void* const* d_in, const int* in_sizes, int n_in,
                              void* d_out, int out_size) {
    (void)in_sizes; (void)n_in; (void)out_size;
    const float* z            = (const float*)d_in[0];
    const float* embedding    = (const float*)d_in[1];
    const float* cluster_size = (const float*)d_in[2];
    const float* ema_w        = (const float*)d_in[3];
    float* out = (float*)d_out;

    cudaFuncSetAttribute(k_dist_mma, cudaFuncAttributeMaxDynamicSharedMemorySize, SM_SZ);

    p_zsplit<<<dim3(32, 8, 16), dim3(32, 8)>>>(z);
    p_esplit<<<1024, 256>>>(embedding);
    k_zero<<<2048, 512>>>();
    k_dist_mma<<<NV / MTOK, 128, SM_SZ>>>(z, embedding, out);
    k_rescue<<<32, 256>>>(z, embedding, out);
    k_scatter<<<dim3(128, 8), 128>>>(z, embedding, out);
    k_cs<<<1, 1024>>>(cluster_size, out);
    k_final<<<8192, 256>>>(ema_w, out);
}

// round 6
// speedup vs baseline: 1273.9990x; 1273.9990x over previous
#include <cuda_runtime.h>
#include <cuda_bf16.h>
#include <cstdint>

// ---------------- problem constants ----------------
#define NV   16384
#define KC   8192
#define DIMV 256
#define HWSZ 1024
#define BDHW (DIMV*HWSZ)

#define DECAYF 0.99f
#define OMDF   0.01f
#define EPSF   1e-5f
#define TCAND  1.5f     // candidate threshold (>= 14 sigma of bf16 1-pass error)
#define CAP    24       // candidate capacity per row

// output layout (float32, concatenated)
#define OUT_OFF  0
#define LOSS_OFF 4194304
#define IDX_OFF  4194305
#define CS_OFF   4210689
#define EMAW_OFF 4218881
#define EMB_OFF  6316033

// ---------------- scratch ----------------
__device__ __nv_bfloat16 g_zh[NV * DIMV];   // token-major bf16 z
__device__ __nv_bfloat16 g_eh[KC * DIMV];   // bf16 codebook
__device__ float  g_enorm[KC];
__device__ int    g_idx[NV];
__device__ float  g_esum[KC * DIMV];
__device__ float  g_counts[KC];
__device__ double g_loss;
__device__ float  g_ncs[KC];
__device__ int    g_nflag;
__device__ int    g_flaglist[NV];

// ---------------- helpers ----------------
__device__ __forceinline__ uint32_t smem_u32(const void* p) {
    uint32_t a;
    asm("{ .reg .u64 t; cvta.to.shared.u64 t, %1; cvt.u32.u64 %0, t; }" : "=r"(a) : "l"(p));
    return a;
}
#define CP_ASYNC16(sm, gp) asm volatile("cp.async.cg.shared.global [%0], [%1], 16;" :: "r"(sm), "l"(gp) : "memory")
#define CP_COMMIT() asm volatile("cp.async.commit_group;" ::: "memory")
#define CP_WAIT1()  asm volatile("cp.async.wait_group 1;" ::: "memory")

__device__ __forceinline__ void ldsm4(uint32_t& r0, uint32_t& r1, uint32_t& r2, uint32_t& r3, uint32_t a) {
    asm volatile("ldmatrix.sync.aligned.m8n8.x4.shared.b16 {%0,%1,%2,%3}, [%4];"
                 : "=r"(r0), "=r"(r1), "=r"(r2), "=r"(r3) : "r"(a));
}
__device__ __forceinline__ void mma16816(float& c0, float& c1, float& c2, float& c3,
                                         uint32_t a0, uint32_t a1, uint32_t a2, uint32_t a3,
                                         uint32_t b0, uint32_t b1) {
    asm volatile("mma.sync.aligned.m16n8k16.row.col.f32.bf16.bf16.f32 "
                 "{%0,%1,%2,%3}, {%4,%5,%6,%7}, {%8,%9}, {%0,%1,%2,%3};"
                 : "+f"(c0), "+f"(c1), "+f"(c2), "+f"(c3)
                 : "r"(a0), "r"(a1), "r"(a2), "r"(a3), "r"(b0), "r"(b1));
}
__device__ __forceinline__ uint32_t fkey(float s) {
    uint32_t b = __float_as_uint(s);
    return (b & 0x80000000u) ? ~b : (b | 0x80000000u);
}
__device__ __forceinline__ float funkey(uint32_t k) {
    return (k & 0x80000000u) ? __uint_as_float(k ^ 0x80000000u) : __uint_as_float(~k);
}

// smem layout (relative to 1024-aligned base). 64 tokens/CTA, NT=64 codes/tile.
// SA doubles as B buffer #2 after A fragments are cached in registers.
#define MTOK   64
#define NT     64
#define TILES  (KC / NT)          // 128
#define SA     0                  // A: 64 x 512B = 32768 (later: B buf 2)
#define SB     32768              // B bufs 0,1: 2 x 32768
#define SROWK  (SB + 65536)       // 64 x u32 = 256
#define SCNT   (SROWK + 256)      // 64 x int = 256
#define SCODE  (SCNT + 256)       // 64 x CAP x 4 = 6144
#define SSV    (SCODE + 64*CAP*4) // 6144
#define SM_SZ  (SSV + 64*CAP*4 + 1024)

// ---------------------------------------------------------------------------
// P1: z [16,256,32,32] -> token-major bf16 (32x32 transpose tiles)
// ---------------------------------------------------------------------------
__global__ void p_zsplit(const float* __restrict__ z) {
    __shared__ float tile[32][33];
    int b = blockIdx.z, d0 = blockIdx.y * 32, hw0 = blockIdx.x * 32;
    int tx = threadIdx.x, ty = threadIdx.y;
    #pragma unroll
    for (int k = 0; k < 4; k++) {
        int d = d0 + ty + k * 8;
        tile[ty + k * 8][tx] = z[b * BDHW + d * HWSZ + hw0 + tx];
    }
    __syncthreads();
    #pragma unroll
    for (int k = 0; k < 4; k++) {
        int hw = hw0 + ty + k * 8;
        int n = b * HWSZ + hw;
        g_zh[n * DIMV + d0 + tx] = __float2bfloat16(tile[tx][ty + k * 8]);
    }
}

// ---------------------------------------------------------------------------
// P2: e -> bf16 + ||e||^2
// ---------------------------------------------------------------------------
__global__ void p_esplit(const float* __restrict__ e) {
    int w = (blockIdx.x * blockDim.x + threadIdx.x) >> 5;
    int lane = threadIdx.x & 31;
    if (w >= KC) return;
    const float* row = e + w * DIMV;
    float s = 0.f;
    #pragma unroll
    for (int i = 0; i < 8; i++) {
        int d = i * 32 + lane;
        float x = row[d];
        g_eh[w * DIMV + d] = __float2bfloat16(x);
        s += x * x;
    }
    #pragma unroll
    for (int o = 16; o; o >>= 1) s += __shfl_xor_sync(0xFFFFFFFFu, s, o);
    if (lane == 0) g_enorm[w] = s;
}

// ---------------------------------------------------------------------------
// K0: zero accumulators
// ---------------------------------------------------------------------------
__global__ void k_zero() {
    int i = blockIdx.x * blockDim.x + threadIdx.x;
    int stride = gridDim.x * blockDim.x;
    for (int j = i; j < KC * DIMV; j += stride) g_esum[j] = 0.f;
    for (int j = i; j < KC; j += stride) g_counts[j] = 0.f;
    if (i == 0) { g_loss = 0.0; g_nflag = 0; }
}

// ---------------------------------------------------------------------------
// K1: bf16 mma.sync GEMM (64 tokens x 8192 codes x 256) + candidate argmin.
// 128 threads = 4 warps, warp grid 2(M) x 2(N), warp tile 32x32, NT=64.
// A fragments cached in 128 registers (loaded once) -> B-only ldsm per tile.
// 3 B buffers (incl. repurposed A smem) -> 2 syncs/tile.
// Epilogue: pass1 shfl-reduced row min -> shared rowk atomicMin (fresh,
// global across threads -> tight threshold); sync; pass2 appends v < rowk+T.
// Exact fp32 re-score of surviving candidates at the end.
// ---------------------------------------------------------------------------
__global__ void __launch_bounds__(128, 2)
k_dist_mma(const float* __restrict__ z, const float* __restrict__ e,
           float* __restrict__ out) {
    extern __shared__ char dsm[];
    uint32_t raw = smem_u32(dsm);
    uint32_t base = (raw + 1023u) & ~1023u;
    char* sm = dsm + (base - raw);

    int tid = threadIdx.x;
    int lane = tid & 31, wid = tid >> 5;
    int wm = wid & 1, wn = wid >> 1;
    int n0 = blockIdx.x * MTOK;

    uint32_t* rowk = (uint32_t*)(sm + SROWK);
    int* cnt_sm = (int*)(sm + SCNT);
    int* scode = (int*)(sm + SCODE);
    float* ssv = (float*)(sm + SSV);

    if (tid < 64) {
        cnt_sm[tid] = 0;
        rowk[tid] = 0xFFFFFFFFu;
    }

    // ---- prologue: A (64 token rows) + B tiles 0,1 via cp.async ----
    #pragma unroll
    for (int i = 0; i < 16; i++) {
        int idx = tid + 128 * i;
        int row = idx >> 5, kc = idx & 31;
        uint32_t sa = base + SA + row * 512 + (((uint32_t)(kc << 4)) ^ ((row & 7) << 4));
        CP_ASYNC16(sa, (const void*)(g_zh + (size_t)(n0 + row) * DIMV + kc * 8));
    }
    #pragma unroll
    for (int i = 0; i < 16; i++) {
        int idx = tid + 128 * i;
        int row = idx >> 5, kc = idx & 31;
        uint32_t sa = base + SB + row * 512 + (((uint32_t)(kc << 4)) ^ ((row & 7) << 4));
        CP_ASYNC16(sa, (const void*)(g_eh + (size_t)row * DIMV + kc * 8));
    }
    CP_COMMIT();     // g0: A + B0
    #pragma unroll
    for (int i = 0; i < 16; i++) {
        int idx = tid + 128 * i;
        int row = idx >> 5, kc = idx & 31;
        uint32_t sa = base + SB + 32768 + row * 512 + (((uint32_t)(kc << 4)) ^ ((row & 7) << 4));
        CP_ASYNC16(sa, (const void*)(g_eh + (size_t)(NT + row) * DIMV + kc * 8));
    }
    CP_COMMIT();     // g1: B1
    CP_WAIT1();      // g0 done: A + B0 resident
    __syncthreads();

    // ldmatrix per-thread address pieces
    int grp = lane >> 3;
    int rA_off = (lane & 7) + ((grp & 1) << 3);
    uint32_t boA = (uint32_t)((grp >> 1) << 4);
    int rB_off = (lane & 7) + ((grp >> 1) << 3);
    uint32_t boB = (uint32_t)((grp & 1) << 4);

    // ---- cache ALL A fragments in registers (done once) ----
    uint32_t aF[128];
    {
        uint32_t aRow[2], aSw[2];
        #pragma unroll
        for (int mf = 0; mf < 2; mf++) {
            int r = wm * 32 + mf * 16 + rA_off;
            aRow[mf] = base + SA + r * 512;
            aSw[mf] = (uint32_t)((r & 7) << 4);
        }
        #pragma unroll
        for (int ks = 0; ks < 16; ks++) {
            uint32_t kb = (uint32_t)(ks * 32);
            #pragma unroll
            for (int mf = 0; mf < 2; mf++) {
                int o = ks * 8 + mf * 4;
                ldsm4(aF[o], aF[o + 1], aF[o + 2], aF[o + 3],
                      aRow[mf] + ((kb + boA) ^ aSw[mf]));
            }
        }
    }
    __syncthreads();   // all A reads done before SA is reused as B buf 2

    // B fragment addressing (relative to buffer base)
    uint32_t bRow[2], bSw[2];
    #pragma unroll
    for (int p = 0; p < 2; p++) {
        int r = wn * 32 + p * 16 + rB_off;
        bRow[p] = r * 512;
        bSw[p] = (uint32_t)((r & 7) << 4);
    }

    // rows owned by this thread: q = mf*2 + h
    int rown[4];
    #pragma unroll
    for (int mf = 0; mf < 2; mf++)
        #pragma unroll
        for (int h = 0; h < 2; h++)
            rown[mf * 2 + h] = wm * 32 + mf * 16 + (lane >> 2) + h * 8;

    int cbase_th = wn * 32 + 2 * (lane & 3);   // + nf*8 + co
    float acc[32];

    // 3-buffer rotation: cur -> nxt1 -> nxt2 (prefetch target = nxt2)
    uint32_t bufCur = base + SB;
    uint32_t bufN1  = base + SB + 32768u;
    uint32_t bufN2  = base + SA;

    for (int t = 0; t < TILES; t++) {
        CP_WAIT1();        // tile t resident
        __syncthreads();   // visible to all; also: all warps past tile t-1 reads

        // prefetch tile t+2 into nxt2 (previous cur, reads long done)
        if (t + 2 < TILES) {
            const __nv_bfloat16* gsrc = g_eh + (size_t)(t + 2) * NT * DIMV;
            #pragma unroll
            for (int i = 0; i < 16; i++) {
                int idx = tid + 128 * i;
                int row = idx >> 5, kc = idx & 31;
                uint32_t sa = bufN2 + row * 512 + (((uint32_t)(kc << 4)) ^ ((row & 7) << 4));
                CP_ASYNC16(sa, (const void*)(gsrc + (size_t)row * DIMV + kc * 8));
            }
        }
        CP_COMMIT();

        // prefetch enorms for this tile
        float en[8];
        #pragma unroll
        for (int nf = 0; nf < 4; nf++)
            #pragma unroll
            for (int co = 0; co < 2; co++)
                en[nf * 2 + co] = __ldg(&g_enorm[t * NT + cbase_th + nf * 8 + co]);

        #pragma unroll
        for (int i = 0; i < 32; i++) acc[i] = 0.f;

        #pragma unroll
        for (int ks = 0; ks < 16; ks++) {
            uint32_t kb = (uint32_t)(ks * 32);
            uint32_t b0[4], b1[4];
            #pragma unroll
            for (int p = 0; p < 2; p++) {
                uint32_t r0, r1, r2, r3;
                ldsm4(r0, r1, r2, r3, bufCur + bRow[p] + ((kb + boB) ^ bSw[p]));
                b0[p * 2] = r0; b1[p * 2] = r1; b0[p * 2 + 1] = r2; b1[p * 2 + 1] = r3;
            }
            #pragma unroll
            for (int mf = 0; mf < 2; mf++) {
                int ao = ks * 8 + mf * 4;
                #pragma unroll
                for (int nf = 0; nf < 4; nf++) {
                    int ix = mf * 16 + nf * 4;
                    mma16816(acc[ix], acc[ix + 1], acc[ix + 2], acc[ix + 3],
                             aF[ao], aF[ao + 1], aF[ao + 2], aF[ao + 3],
                             b0[nf], b1[nf]);
                }
            }
        }

        // ---- pass 1: convert to distances, row mins -> shared rowk ----
        float tmin[4];
        #pragma unroll
        for (int mf = 0; mf < 2; mf++)
            #pragma unroll
            for (int h = 0; h < 2; h++) {
                int q = mf * 2 + h;
                float m = 3.4e38f;
                #pragma unroll
                for (int nf = 0; nf < 4; nf++)
                    #pragma unroll
                    for (int co = 0; co < 2; co++) {
                        int ix = mf * 16 + nf * 4 + h * 2 + co;
                        float v = fmaf(-2.f, acc[ix], en[nf * 2 + co]);
                        acc[ix] = v;
                        m = fminf(m, v);
                    }
                tmin[q] = m;
                // reduce across the 4 lanes sharing this row (lanes differ in lane&3)
                m = fminf(m, __shfl_xor_sync(0xFFFFFFFFu, m, 1));
                m = fminf(m, __shfl_xor_sync(0xFFFFFFFFu, m, 2));
                if ((lane & 3) == 0) atomicMin(&rowk[rown[q]], fkey(m));
            }
        __syncthreads();   // fresh rowk visible

        // ---- pass 2: append candidates against tight threshold ----
        #pragma unroll
        for (int mf = 0; mf < 2; mf++)
            #pragma unroll
            for (int h = 0; h < 2; h++) {
                int q = mf * 2 + h;
                int r = rown[q];
                float thf = funkey(rowk[r]) + TCAND;
                if (tmin[q] < thf) {
                    #pragma unroll
                    for (int nf = 0; nf < 4; nf++)
                        #pragma unroll
                        for (int co = 0; co < 2; co++) {
                            float v = acc[mf * 16 + nf * 4 + h * 2 + co];
                            if (v < thf) {
                                int code = t * NT + cbase_th + nf * 8 + co;
                                int p = atomicAdd(&cnt_sm[r], 1);
                                if (p < CAP) { scode[r * CAP + p] = code; ssv[r * CAP + p] = v; }
                            }
                        }
                }
            }

        // rotate buffers
        uint32_t tmp = bufCur; bufCur = bufN1; bufN1 = bufN2; bufN2 = tmp;
    }

    __syncthreads();

    // ---- phase 3: exact fp32 re-score of surviving candidates ----
    if (tid < 64) {
        int token = n0 + tid;
        int c = cnt_sm[tid];
        if (c > CAP) {
            int fi = atomicAdd(&g_nflag, 1);
            g_flaglist[fi] = token;
            c = CAP;
        }
        float th = funkey(rowk[tid]) + TCAND;
        int b = token >> 10, hw = token & 1023;
        const float* zb = z + (size_t)b * BDHW + hw;
        float bestS = 3.4e38f; int bestC = 0x7fffffff;
        for (int i = 0; i < c; i++) {
            if (ssv[tid * CAP + i] <= th) {
                int code = scode[tid * CAP + i];
                const float* er = e + (size_t)code * DIMV;
                float dot = 0.f;
                #pragma unroll 8
                for (int d = 0; d < DIMV; d++) dot = fmaf(zb[d * HWSZ], er[d], dot);
                float s = __ldg(&g_enorm[code]) - 2.f * dot;
                if (s < bestS || (s == bestS && code < bestC)) { bestS = s; bestC = code; }
            }
        }
        g_idx[token] = bestC;
        out[IDX_OFF + token] = (float)bestC;
    }
}

// ---------------------------------------------------------------------------
// K1b: rescue — exact full scan for overflowed tokens (expected none)
// ---------------------------------------------------------------------------
__global__ void __launch_bounds__(256)
k_rescue(const float* __restrict__ z, const float* __restrict__ e,
         float* __restrict__ out) {
    __shared__ float zr[256];
    __shared__ unsigned long long red[256];
    int nf = g_nflag;
    for (int f = blockIdx.x; f < nf; f += gridDim.x) {
        int token = g_flaglist[f];
        int b = token >> 10, hw = token & 1023;
        zr[threadIdx.x] = z[(size_t)b * BDHW + threadIdx.x * HWSZ + hw];
        __syncthreads();
        unsigned long long best = 0xFFFFFFFFFFFFFFFFull;
        for (int c = threadIdx.x; c < KC; c += 256) {
            const float* er = e + (size_t)c * DIMV;
            float dot = 0.f;
            #pragma unroll 8
            for (int d = 0; d < DIMV; d++) dot = fmaf(zr[d], er[d], dot);
            float s = g_enorm[c] - 2.f * dot;
            unsigned long long p = ((unsigned long long)fkey(s) << 32) | (unsigned int)c;
            best = min(best, p);
        }
        red[threadIdx.x] = best;
        __syncthreads();
        for (int s = 128; s; s >>= 1) {
            if (threadIdx.x < s) red[threadIdx.x] = min(red[threadIdx.x], red[threadIdx.x + s]);
            __syncthreads();
        }
        if (threadIdx.x == 0) {
            int bc = (int)(red[0] & 0xFFFFFFFFu);
            g_idx[token] = bc;
            out[IDX_OFF + token] = (float)bc;
        }
        __syncthreads();
    }
}

// ---------------------------------------------------------------------------
// K2: gather/scatter. grid (token_block, d_chunk of 32)
// ---------------------------------------------------------------------------
__global__ void __launch_bounds__(128)
k_scatter(const float* __restrict__ z, const float* __restrict__ e,
          float* __restrict__ out) {
    int t = threadIdx.x;
    int n = blockIdx.x * 128 + t;
    int d0 = blockIdx.y * 32;
    int idx = g_idx[n];
    if (blockIdx.y == 0) atomicAdd(&g_counts[idx], 1.f);

    int b = n >> 10, hw = n & 1023;
    const float* zb = z + (size_t)b * BDHW + hw;
    float*       ob = out + OUT_OFF + (size_t)b * BDHW + hw;
    const float* er = e + (size_t)idx * DIMV;
    float* es = g_esum + (size_t)idx * DIMV;

    float lacc = 0.f;
    #pragma unroll
    for (int i = 0; i < 32; i++) {
        int d = d0 + i;
        float zv = zb[d * HWSZ];
        float diff = er[d] - zv;
        lacc += diff * diff;
        ob[d * HWSZ] = zv + diff;
        atomicAdd(&es[d], zv);
    }

    __shared__ float red[128];
    red[t] = lacc;
    __syncthreads();
    #pragma unroll
    for (int s = 64; s; s >>= 1) {
        if (t < s) red[t] += red[t + s];
        __syncthreads();
    }
    if (t == 0) atomicAdd(&g_loss, (double)red[0]);
}

// ---------------------------------------------------------------------------
// K3: cluster-size EMA + denom + loss finalize
// ---------------------------------------------------------------------------
__global__ void __launch_bounds__(1024)
k_cs(const float* __restrict__ cluster_size, float* __restrict__ out) {
    __shared__ float red[1024];
    int t = threadIdx.x;
    float csl[8];
    float local = 0.f;
    #pragma unroll
    for (int r = 0; r < 8; r++) {
        int k = t * 8 + r;
        float cs = cluster_size[k] * DECAYF + OMDF * g_counts[k] + EPSF;
        csl[r] = cs;
        local += cs;
    }
    red[t] = local;
    __syncthreads();
    #pragma unroll
    for (int s = 512; s; s >>= 1) {
        if (t < s) red[t] += red[t + s];
        __syncthreads();
    }
    float denom = red[0] + (float)(KC * 1e-05);
    #pragma unroll
    for (int r = 0; r < 8; r++) {
        int k = t * 8 + r;
        float v = csl[r] / denom;
        g_ncs[k] = v;
        out[CS_OFF + k] = v;
    }
    if (t == 0)
        out[LOSS_OFF] = (float)(0.25 * g_loss / (double)((size_t)NV * DIMV));
}

// ---------------------------------------------------------------------------
// K4: new_ema_w and new_embedding
// ---------------------------------------------------------------------------
__global__ void k_final(const float* __restrict__ ema_w, float* __restrict__ out) {
    int i = blockIdx.x * blockDim.x + threadIdx.x;
    if (i >= KC * DIMV) return;
    int k = i >> 8;
    float v = ema_w[i] * DECAYF + OMDF * g_esum[i];
    out[EMAW_OFF + i] = v;
    out[EMB_OFF + i]  = v / g_ncs[k];
}

// ---------------------------------------------------------------------------
extern "C" void kernel_launch(void* const* d_in, const int* in_sizes, int n_in,
                              void* d_out, int out_size) {
    (void)in_sizes; (void)n_in; (void)out_size;
    const float* z            = (const float*)d_in[0];
    const float* embedding    = (const float*)d_in[1];
    const float* cluster_size = (const float*)d_in[2];
    const float* ema_w        = (const float*)d_in[3];
    float* out = (float*)d_out;

    cudaFuncSetAttribute(k_dist_mma, cudaFuncAttributeMaxDynamicSharedMemorySize, SM_SZ);

    p_zsplit<<<dim3(32, 8, 16), dim3(32, 8)>>>(z);
    p_esplit<<<1024, 256>>>(embedding);
    k_zero<<<2048, 512>>>();
    k_dist_mma<<<NV / MTOK, 128, SM_SZ>>>(z, embedding, out);
    k_rescue<<<32, 256>>>(z, embedding, out);
    k_scatter<<<dim3(128, 8), 128>>>(z, embedding, out);
    k_cs<<<1, 1024>>>(cluster_size, out);
    k_final<<<8192, 256>>>(ema_w, out);
}